// round 10
// baseline (speedup 1.0000x reference)
#include <cuda_runtime.h>

// Problem constants (fixed by the reference)
#define BATCH 16384
#define DIM   2048
#define NUMCL 1000

#define CHUNK   512                    // floats per column tile
#define NCHUNK  (DIM / CHUNK)          // 4
#define THREADS 256
#define NWARPS  8192
#define NBLOCKS (NWARPS / 8)           // 1024
#define TASKS_PER_WARP (BATCH * NCHUNK / NWARPS)  // 8

// Per-row partial accumulators and completion counters.
// Uninitialized __device__ globals are zero-filled at load; the finalizer
// resets everything it consumes, so the zero invariant holds across replays.
__device__ float        g_part[BATCH][4];   // dot, ss, tt, cc
__device__ unsigned int g_cnt[BATCH];
__device__ float        g_accum;
__device__ unsigned int g_rows_done;

__device__ __forceinline__ float dot4(const float4& x, const float4& y, float acc) {
    return fmaf(x.x, y.x, fmaf(x.y, y.y, fmaf(x.z, y.z, fmaf(x.w, y.w, acc))));
}

// ---------------------------------------------------------------------------
// Column-tiled fused kernel. Each warp runs 8 tasks; task t = warp + i*NWARPS
// maps to (chunk = t / BATCH, row = t % BATCH), so the whole GPU sweeps
// chunk 0 -> 1 -> 2 -> 3 roughly in lockstep: the active T_EMB slice is
// ~2 MB at any instant, so class centers stay L2-resident between touches.
// ---------------------------------------------------------------------------
__global__ __launch_bounds__(THREADS, 8)
void dnl_tiled_kernel(const float* __restrict__ s_emb,
                      const float* __restrict__ t_emb,
                      const float* __restrict__ T_EMB,
                      const int*   __restrict__ labels,
                      float*       __restrict__ out)
{
    const int warp  = threadIdx.x >> 5;
    const int lane  = threadIdx.x & 31;
    const int gwarp = blockIdx.x * 8 + warp;            // 0..8191

    #pragma unroll
    for (int i = 0; i < TASKS_PER_WARP; ++i) {
        const int task  = gwarp + i * NWARPS;           // 0..65535
        const int chunk = task >> 14;                   // task / BATCH
        const int row   = task & (BATCH - 1);           // task % BATCH

        const size_t base = (size_t)row * DIM + (size_t)chunk * CHUNK;
        const float4* __restrict__ s = (const float4*)(s_emb + base);
        const float4* __restrict__ t = (const float4*)(t_emb + base);

        // labels are int32 (JAX x64-disabled downcasts the reference's int64).
        int lbl = labels[row];
        lbl = (lbl < 0) ? 0 : ((lbl >= NUMCL) ? (NUMCL - 1) : lbl);
        const float4* __restrict__ c =
            (const float4*)(T_EMB + (size_t)lbl * DIM + (size_t)chunk * CHUNK);

        float dot = 0.f, ss = 0.f, tt = 0.f, cc = 0.f;

        // CHUNK/4 = 128 float4; 32 lanes -> 4 per lane
        #pragma unroll
        for (int j = 0; j < 4; ++j) {
            const int idx = j * 32 + lane;
            const float4 sv = __ldcs(&s[idx]);   // stream-once
            const float4 tv = __ldcs(&t[idx]);   // stream-once
            const float4 cv = __ldg (&c[idx]);   // hot 2 MB slice in L2
            dot = dot4(sv, cv, dot);
            ss  = dot4(sv, sv, ss);
            tt  = dot4(tv, tv, tt);
            cc  = dot4(cv, cv, cc);
        }

        // Warp tree-reduce
        #pragma unroll
        for (int off = 16; off > 0; off >>= 1) {
            dot += __shfl_xor_sync(0xFFFFFFFFu, dot, off);
            ss  += __shfl_xor_sync(0xFFFFFFFFu, ss,  off);
            tt  += __shfl_xor_sync(0xFFFFFFFFu, tt,  off);
            cc  += __shfl_xor_sync(0xFFFFFFFFu, cc,  off);
        }

        if (lane == 0) {
            atomicAdd(&g_part[row][0], dot);
            atomicAdd(&g_part[row][1], ss);
            atomicAdd(&g_part[row][2], tt);
            atomicAdd(&g_part[row][3], cc);
            __threadfence();
            // 4th finisher (rank 3) finalizes this row; counter wraps to 0.
            unsigned int rank = atomicInc(&g_cnt[row], NCHUNK - 1);
            if (rank == NCHUNK - 1) {
                __threadfence();
                volatile float* p = g_part[row];
                const float rdot = p[0], rss = p[1], rtt = p[2], rcc = p[3];
                // reset row state for next replay
                p[0] = 0.f; p[1] = 0.f; p[2] = 0.f; p[3] = 0.f;

                const float max_norm = fmaxf(sqrtf(rss), sqrtf(rtt));
                const float loss = 1.0f - rdot / (sqrtf(rcc) * max_norm);
                atomicAdd(&g_accum, loss);
                __threadfence();
                unsigned int rr = atomicInc(&g_rows_done, BATCH - 1);
                if (rr == BATCH - 1) {
                    __threadfence();
                    float total = *(volatile float*)&g_accum;
                    out[0] = total * (1.0f / (float)BATCH);  // ND_WEIGHT = 1
                    g_accum = 0.0f;                          // replay reset
                }
            }
        }
    }
}

// ---------------------------------------------------------------------------
// kernel_launch: graph-capturable, allocation-free, single launch.
// Inputs (metadata order): s_emb f32[B*D], t_emb f32[B*D],
//                          T_EMB f32[NUMCL*D], labels i32[B]
// Output: f32 scalar
// ---------------------------------------------------------------------------
extern "C" void kernel_launch(void* const* d_in, const int* in_sizes, int n_in,
                              void* d_out, int out_size)
{
    const float* s_emb  = (const float*)d_in[0];
    const float* t_emb  = (const float*)d_in[1];
    const float* T_EMB  = (const float*)d_in[2];
    const int*   labels = (const int*)d_in[3];
    float* out = (float*)d_out;

    dnl_tiled_kernel<<<NBLOCKS, THREADS>>>(s_emb, t_emb, T_EMB, labels, out);
}

// round 11
// speedup vs baseline: 1.6467x; 1.6467x over previous
#include <cuda_runtime.h>

// Problem constants (fixed by the reference)
#define BATCH 16384
#define DIM   2048
#define NUMCL 1000

#define THREADS 256                   // 8 warps per block
#define NWARPS  8192                  // each warp owns rows w and w+8192
#define NBLOCKS (NWARPS / 8)          // 1024 blocks -> single uniform wave @occ7

// Fused-reduction state (allocation-free rule: __device__ globals).
__device__ float        g_accum  = 0.0f;
__device__ unsigned int g_ticket = 0;

__device__ __forceinline__ float dot4(const float4& x, const float4& y, float acc) {
    return fmaf(x.x, y.x, fmaf(x.y, y.y, fmaf(x.z, y.z, fmaf(x.w, y.w, acc))));
}

// ---------------------------------------------------------------------------
// R8 schedule, but the warp's two rows are processed INTERLEAVED in two
// phases to double the independent load streams per dependency window:
//   phase 1: s0,c0,s1,c1  (dot/ss/cc for both rows)
//   phase 2: t0,t1        (tt for both rows)
// Byte traffic identical to R8 (float4, __ldcs streams, __ldg centers).
// ---------------------------------------------------------------------------
__global__ __launch_bounds__(THREADS, 7)
void dnl_fused_kernel(const float* __restrict__ s_emb,
                      const float* __restrict__ t_emb,
                      const float* __restrict__ T_EMB,
                      const int*   __restrict__ labels,
                      float*       __restrict__ out)
{
    const int warp  = threadIdx.x >> 5;                 // 0..7
    const int lane  = threadIdx.x & 31;
    const int gwarp = blockIdx.x * 8 + warp;            // 0..8191

    const int row0 = gwarp;
    const int row1 = gwarp + NWARPS;

    // labels are int32 (JAX x64-disabled downcasts the reference's int64).
    int l0 = labels[row0];
    int l1 = labels[row1];
    l0 = (l0 < 0) ? 0 : ((l0 >= NUMCL) ? (NUMCL - 1) : l0);
    l1 = (l1 < 0) ? 0 : ((l1 >= NUMCL) ? (NUMCL - 1) : l1);

    const float4* __restrict__ s0 = (const float4*)(s_emb + (size_t)row0 * DIM);
    const float4* __restrict__ s1 = (const float4*)(s_emb + (size_t)row1 * DIM);
    const float4* __restrict__ c0 = (const float4*)(T_EMB + (size_t)l0 * DIM);
    const float4* __restrict__ c1 = (const float4*)(T_EMB + (size_t)l1 * DIM);

    float dot0 = 0.f, ss0 = 0.f, cc0 = 0.f;
    float dot1 = 0.f, ss1 = 0.f, cc1 = 0.f;

    // Phase 1: s and c for both rows (4 independent streams)
    #pragma unroll
    for (int i = 0; i < 16; ++i) {
        const int idx = i * 32 + lane;
        const float4 sv0 = __ldcs(&s0[idx]);
        const float4 sv1 = __ldcs(&s1[idx]);
        const float4 cv0 = __ldg (&c0[idx]);
        const float4 cv1 = __ldg (&c1[idx]);
        dot0 = dot4(sv0, cv0, dot0);
        dot1 = dot4(sv1, cv1, dot1);
        ss0  = dot4(sv0, sv0, ss0);
        ss1  = dot4(sv1, sv1, ss1);
        cc0  = dot4(cv0, cv0, cc0);
        cc1  = dot4(cv1, cv1, cc1);
    }

    // Phase 2: t for both rows
    const float4* __restrict__ t0 = (const float4*)(t_emb + (size_t)row0 * DIM);
    const float4* __restrict__ t1 = (const float4*)(t_emb + (size_t)row1 * DIM);
    float tt0 = 0.f, tt1 = 0.f;
    #pragma unroll
    for (int i = 0; i < 16; ++i) {
        const int idx = i * 32 + lane;
        const float4 tv0 = __ldcs(&t0[idx]);
        const float4 tv1 = __ldcs(&t1[idx]);
        tt0 = dot4(tv0, tv0, tt0);
        tt1 = dot4(tv1, tv1, tt1);
    }

    // Warp tree-reduce all 8 accumulators
    #pragma unroll
    for (int off = 16; off > 0; off >>= 1) {
        dot0 += __shfl_xor_sync(0xFFFFFFFFu, dot0, off);
        ss0  += __shfl_xor_sync(0xFFFFFFFFu, ss0,  off);
        cc0  += __shfl_xor_sync(0xFFFFFFFFu, cc0,  off);
        tt0  += __shfl_xor_sync(0xFFFFFFFFu, tt0,  off);
        dot1 += __shfl_xor_sync(0xFFFFFFFFu, dot1, off);
        ss1  += __shfl_xor_sync(0xFFFFFFFFu, ss1,  off);
        cc1  += __shfl_xor_sync(0xFFFFFFFFu, cc1,  off);
        tt1  += __shfl_xor_sync(0xFFFFFFFFu, tt1,  off);
    }

    // Block-level: 8 per-warp losses -> one sum
    __shared__ float sh_loss[8];
    if (lane == 0) {
        const float mn0 = fmaxf(sqrtf(ss0), sqrtf(tt0));
        const float mn1 = fmaxf(sqrtf(ss1), sqrtf(tt1));
        sh_loss[warp] = (1.0f - dot0 / (sqrtf(cc0) * mn0))
                      + (1.0f - dot1 / (sqrtf(cc1) * mn1));
    }
    __syncthreads();

    if (threadIdx.x == 0) {
        float bsum = sh_loss[0] + sh_loss[1] + sh_loss[2] + sh_loss[3]
                   + sh_loss[4] + sh_loss[5] + sh_loss[6] + sh_loss[7];
        atomicAdd(&g_accum, bsum);

        // Make the add visible before taking a ticket
        __threadfence();
        unsigned int rank = atomicInc(&g_ticket, NBLOCKS - 1);  // wraps to 0
        if (rank == NBLOCKS - 1) {
            float total = *(volatile float*)&g_accum;
            out[0] = total * (1.0f / (float)BATCH);   // ND_WEIGHT = 1
            g_accum = 0.0f;                           // reset for next replay
        }
    }
}

// ---------------------------------------------------------------------------
// kernel_launch: graph-capturable, allocation-free, single launch.
// Inputs (metadata order): s_emb f32[B*D], t_emb f32[B*D],
//                          T_EMB f32[NUMCL*D], labels i32[B]
// Output: f32 scalar
// ---------------------------------------------------------------------------
extern "C" void kernel_launch(void* const* d_in, const int* in_sizes, int n_in,
                              void* d_out, int out_size)
{
    const float* s_emb  = (const float*)d_in[0];
    const float* t_emb  = (const float*)d_in[1];
    const float* T_EMB  = (const float*)d_in[2];
    const int*   labels = (const int*)d_in[3];
    float* out = (float*)d_out;

    dnl_fused_kernel<<<NBLOCKS, THREADS>>>(s_emb, t_emb, T_EMB, labels, out);
}